// round 12
// baseline (speedup 1.0000x reference)
#include <cuda_runtime.h>

// Fully-fused 4-level 2D Haar DWT — R2 body + streaming cache hints.
// Input x: (32, 3, 512, 512) fp32.
// Output: concat of t1 (32,12,256,256), t2 (32,12,128,128),
//         t3 (32,12,64,64), t4 (32,12,32,32).
// One block = one 128x128 input tile of one (batch,color) plane; LL bands
// cascade through shared memory, so every global store is write-once and
// every input byte is read-once: __ldcs / __stcs keep L2 evict-first, letting
// the dirty-writeback overlap kernel execution (steady-state replay win).
// Level 4 computes r,g only (b4 = g4 duplicated into channels 8..11).

#define HAAR(a_, b_, c_, d_, LL, LH, HL, HH)      \
    do {                                          \
        float L0 = (a_ + c_) * 0.5f;              \
        float L1 = (b_ + d_) * 0.5f;              \
        float H0 = fabsf(a_ - c_);                \
        float H1 = fabsf(b_ - d_);                \
        LL = (L0 + L1) * 0.5f;                    \
        LH = fabsf(L0 - L1);                      \
        HL = (H0 + H1) * 0.5f;                    \
        HH = fabsf(H0 - H1);                      \
    } while (0)

__global__ __launch_bounds__(256) void dwt_fused_kernel(
    const float* __restrict__ x, float* __restrict__ out)
{
    __shared__ float s1[64 * 64];   // 16 KB, L1 LL
    __shared__ float s2[32 * 32];   //  4 KB, L2 LL
    __shared__ float s3[16 * 16];   //  1 KB, L3 LL

    const int tid = threadIdx.x;
    const int tj  = blockIdx.x;       // 0..3  (column tile)
    const int ti  = blockIdx.y;       // 0..3  (row tile)
    const int bc  = blockIdx.z;       // 0..95
    const int b   = bc / 3;
    const int c   = bc % 3;

    const long S1 = 32L * 12 * 256 * 256;
    const long S2 = 32L * 12 * 128 * 128;
    const long S3 = 32L * 12 * 64 * 64;

    // ---------------- Level 1: x -> t1 (64x64 outputs) ---------------------
    {
        const float* ip = x + (long)b * (3 * 512 * 512)
                            + (long)c * (512 * 512)
                            + (long)(ti * 128) * 512 + tj * 128;
        float* o1 = out + (long)b * (12 * 65536)
                        + (long)(c * 4) * 65536
                        + (long)(ti * 64) * 256 + tj * 64;

        const int tx = tid & 63;       // column 0..63
        const int ty = tid >> 6;       // 0..3

        #pragma unroll
        for (int r = ty; r < 64; r += 4) {
            const float2* r0 = reinterpret_cast<const float2*>(ip + (long)(2 * r) * 512);
            const float2* r1 = reinterpret_cast<const float2*>(ip + (long)(2 * r + 1) * 512);
            float2 t = __ldcs(&r0[tx]);
            float2 u = __ldcs(&r1[tx]);

            float LL, LH, HL, HH;
            HAAR(t.x, t.y, u.x, u.y, LL, LH, HL, HH);

            float* orow = o1 + (long)r * 256 + tx;
            __stcs(orow,             LL);
            __stcs(orow + 65536,     LH);
            __stcs(orow + 2 * 65536, HL);
            __stcs(orow + 3 * 65536, HH);
            s1[r * 64 + tx] = LL;
        }
    }
    __syncthreads();

    // ---------------- Level 2: s1 -> t2 (32x32 outputs) --------------------
    {
        float* o2 = out + S1 + (long)b * (12 * 16384)
                        + (long)(c * 4) * 16384
                        + (long)(ti * 32) * 128 + tj * 32;

        const int tx = tid & 31;       // column 0..31
        const int ty = tid >> 5;       // 0..7
        const float2* s1v = reinterpret_cast<const float2*>(s1);

        #pragma unroll
        for (int r = ty; r < 32; r += 8) {
            float2 t = s1v[(2 * r) * 32 + tx];
            float2 u = s1v[(2 * r + 1) * 32 + tx];

            float LL, LH, HL, HH;
            HAAR(t.x, t.y, u.x, u.y, LL, LH, HL, HH);

            float* orow = o2 + (long)r * 128 + tx;
            __stcs(orow,             LL);
            __stcs(orow + 16384,     LH);
            __stcs(orow + 2 * 16384, HL);
            __stcs(orow + 3 * 16384, HH);
            s2[r * 32 + tx] = LL;
        }
    }
    __syncthreads();

    // ---------------- Level 3: s2 -> t3 (16x16 outputs) --------------------
    {
        float* o3 = out + S1 + S2 + (long)b * (12 * 4096)
                        + (long)(c * 4) * 4096
                        + (long)(ti * 16) * 64 + tj * 16;

        const int tx = tid & 15;       // 0..15
        const int ty = tid >> 4;       // 0..15
        const float2* s2v = reinterpret_cast<const float2*>(s2);

        float2 t = s2v[(2 * ty) * 16 + tx];
        float2 u = s2v[(2 * ty + 1) * 16 + tx];

        float LL, LH, HL, HH;
        HAAR(t.x, t.y, u.x, u.y, LL, LH, HL, HH);

        float* orow = o3 + (long)ty * 64 + tx;
        __stcs(orow,            LL);
        __stcs(orow + 4096,     LH);
        __stcs(orow + 2 * 4096, HL);
        __stcs(orow + 3 * 4096, HH);
        s3[ty * 16 + tx] = LL;
    }
    __syncthreads();

    // ---------------- Level 4: s3 -> t4 (8x8 outputs, r/g only) ------------
    if (tid < 64 && c < 2) {
        float* o4 = out + S1 + S2 + S3 + (long)b * (12 * 1024)
                        + (long)(c * 4) * 1024
                        + (long)(ti * 8) * 32 + tj * 8;

        const int tx = tid & 7;        // 0..7
        const int ty = tid >> 3;       // 0..7
        const float2* s3v = reinterpret_cast<const float2*>(s3);

        float2 t = s3v[(2 * ty) * 8 + tx];
        float2 u = s3v[(2 * ty + 1) * 8 + tx];

        float LL, LH, HL, HH;
        HAAR(t.x, t.y, u.x, u.y, LL, LH, HL, HH);

        float* orow = o4 + (long)ty * 32 + tx;
        __stcs(orow,            LL);
        __stcs(orow + 1024,     LH);
        __stcs(orow + 2 * 1024, HL);
        __stcs(orow + 3 * 1024, HH);

        if (c == 1) {                  // b4 = g4 -> channels 8..11
            float* orow2 = orow + 4 * 1024;
            __stcs(orow2,            LL);
            __stcs(orow2 + 1024,     LH);
            __stcs(orow2 + 2 * 1024, HL);
            __stcs(orow2 + 3 * 1024, HH);
        }
    }
}

extern "C" void kernel_launch(void* const* d_in, const int* in_sizes, int n_in,
                              void* d_out, int out_size)
{
    const float* x = (const float*)d_in[0];
    float* out = (float*)d_out;

    dim3 block(256, 1, 1);
    dim3 grid(4, 4, 96);
    dwt_fused_kernel<<<grid, block>>>(x, out);
}

// round 13
// speedup vs baseline: 1.0897x; 1.0897x over previous
#include <cuda_runtime.h>

// Fully-fused 4-level 2D Haar DWT — float4 + streaming .cs stores (R3 body)
// with register cap for 7 blocks/SM occupancy.
// Input x: (32, 3, 512, 512) fp32.
// Output: concat of t1 (32,12,256,256), t2 (32,12,128,128),
//         t3 (32,12,64,64), t4 (32,12,32,32).
// One block = one 128x128 input tile of one (batch,color) plane; LL bands
// cascade through shared memory. All global stores are STG.128 + .cs
// (full-sector non-temporal writes -> overlapped L2 writeback, measured
// wall-kernel gap 7.3us vs 9.0us for plain scalar stores).
// Level 4 computes r,g only (b4 = g4 duplicated into channels 8..11).

#define HAAR(a_, b_, c_, d_, LL, LH, HL, HH)      \
    do {                                          \
        float L0 = (a_ + c_) * 0.5f;              \
        float L1 = (b_ + d_) * 0.5f;              \
        float H0 = fabsf(a_ - c_);                \
        float H1 = fabsf(b_ - d_);                \
        LL = (L0 + L1) * 0.5f;                    \
        LH = fabsf(L0 - L1);                      \
        HL = (H0 + H1) * 0.5f;                    \
        HH = fabsf(H0 - H1);                      \
    } while (0)

// 4 horizontal Haar butterflies from two float4 row segments.
#define HAAR4(p0, p1, q0, q1, LL, LH, HL, HH)                     \
    do {                                                          \
        HAAR(p0.x, p0.y, q0.x, q0.y, LL.x, LH.x, HL.x, HH.x);     \
        HAAR(p0.z, p0.w, q0.z, q0.w, LL.y, LH.y, HL.y, HH.y);     \
        HAAR(p1.x, p1.y, q1.x, q1.y, LL.z, LH.z, HL.z, HH.z);     \
        HAAR(p1.z, p1.w, q1.z, q1.w, LL.w, LH.w, HL.w, HH.w);     \
    } while (0)

__global__ __launch_bounds__(256, 7) void dwt_fused_kernel(
    const float* __restrict__ x, float* __restrict__ out)
{
    __shared__ float s1[64 * 64];   // 16 KB, L1 LL
    __shared__ float s2[32 * 32];   //  4 KB, L2 LL
    __shared__ float s3[16 * 16];   //  1 KB, L3 LL

    const int tid = threadIdx.x;
    const int tj  = blockIdx.x;       // 0..3
    const int ti  = blockIdx.y;       // 0..3
    const int bc  = blockIdx.z;       // 0..95
    const int b   = bc / 3;
    const int c   = bc % 3;

    const long S1 = 32L * 12 * 256 * 256;
    const long S2 = 32L * 12 * 128 * 128;
    const long S3 = 32L * 12 * 64 * 64;

    // ---- Level 1: x -> t1. 4 output px/thread/iter, LDG.128 / STG.128 ----
    {
        const float* ip = x + (long)b * (3 * 512 * 512)
                            + (long)c * (512 * 512)
                            + (long)(ti * 128) * 512 + tj * 128;
        float* o1 = out + (long)b * (12 * 65536)
                        + (long)(c * 4) * 65536
                        + (long)(ti * 64) * 256 + tj * 64;

        const int tx = tid & 15;      // 16 thread-cols * 4 out px = 64
        const int ty = tid >> 4;      // 0..15

        #pragma unroll
        for (int r = ty; r < 64; r += 16) {     // 4 iterations
            const float4* r0 = reinterpret_cast<const float4*>(ip + (long)(2 * r) * 512);
            const float4* r1 = reinterpret_cast<const float4*>(ip + (long)(2 * r + 1) * 512);
            float4 p0 = __ldcs(&r0[2 * tx]);
            float4 p1 = __ldcs(&r0[2 * tx + 1]);
            float4 q0 = __ldcs(&r1[2 * tx]);
            float4 q1 = __ldcs(&r1[2 * tx + 1]);

            float4 LL, LH, HL, HH;
            HAAR4(p0, p1, q0, q1, LL, LH, HL, HH);

            float* orow = o1 + (long)r * 256 + tx * 4;
            __stcs(reinterpret_cast<float4*>(orow),              LL);
            __stcs(reinterpret_cast<float4*>(orow + 65536),      LH);
            __stcs(reinterpret_cast<float4*>(orow + 2 * 65536),  HL);
            __stcs(reinterpret_cast<float4*>(orow + 3 * 65536),  HH);
            *reinterpret_cast<float4*>(&s1[r * 64 + tx * 4]) = LL;
        }
    }
    __syncthreads();

    // ---- Level 2: s1 (64x64) -> t2. 32x32 outputs, 4 px/thread, 1 iter ---
    {
        float* o2 = out + S1 + (long)b * (12 * 16384)
                        + (long)(c * 4) * 16384
                        + (long)(ti * 32) * 128 + tj * 32;

        const int tx = tid & 7;       // 8 thread-cols * 4 px = 32
        const int ty = tid >> 3;      // 0..31 (= output row)

        const float4* s1v = reinterpret_cast<const float4*>(s1);  // 16 f4/row
        float4 p0 = s1v[(2 * ty) * 16 + 2 * tx];
        float4 p1 = s1v[(2 * ty) * 16 + 2 * tx + 1];
        float4 q0 = s1v[(2 * ty + 1) * 16 + 2 * tx];
        float4 q1 = s1v[(2 * ty + 1) * 16 + 2 * tx + 1];

        float4 LL, LH, HL, HH;
        HAAR4(p0, p1, q0, q1, LL, LH, HL, HH);

        float* orow = o2 + (long)ty * 128 + tx * 4;
        __stcs(reinterpret_cast<float4*>(orow),              LL);
        __stcs(reinterpret_cast<float4*>(orow + 16384),      LH);
        __stcs(reinterpret_cast<float4*>(orow + 2 * 16384),  HL);
        __stcs(reinterpret_cast<float4*>(orow + 3 * 16384),  HH);
        *reinterpret_cast<float4*>(&s2[ty * 32 + tx * 4]) = LL;
    }
    __syncthreads();

    // ---- Level 3: s2 (32x32) -> t3. 16x16 outputs, 4 px/thread, tid<64 ---
    if (tid < 64) {
        float* o3 = out + S1 + S2 + (long)b * (12 * 4096)
                        + (long)(c * 4) * 4096
                        + (long)(ti * 16) * 64 + tj * 16;

        const int tx = tid & 3;       // 4 thread-cols * 4 px = 16
        const int ty = tid >> 2;      // 0..15

        const float4* s2v = reinterpret_cast<const float4*>(s2);  // 8 f4/row
        float4 p0 = s2v[(2 * ty) * 8 + 2 * tx];
        float4 p1 = s2v[(2 * ty) * 8 + 2 * tx + 1];
        float4 q0 = s2v[(2 * ty + 1) * 8 + 2 * tx];
        float4 q1 = s2v[(2 * ty + 1) * 8 + 2 * tx + 1];

        float4 LL, LH, HL, HH;
        HAAR4(p0, p1, q0, q1, LL, LH, HL, HH);

        float* orow = o3 + (long)ty * 64 + tx * 4;
        __stcs(reinterpret_cast<float4*>(orow),             LL);
        __stcs(reinterpret_cast<float4*>(orow + 4096),      LH);
        __stcs(reinterpret_cast<float4*>(orow + 2 * 4096),  HL);
        __stcs(reinterpret_cast<float4*>(orow + 3 * 4096),  HH);
        *reinterpret_cast<float4*>(&s3[ty * 16 + tx * 4]) = LL;
    }
    __syncthreads();

    // ---- Level 4: s3 (16x16) -> t4. 8x8 outputs, r/g only, tid<16 --------
    if (tid < 16 && c < 2) {
        float* o4 = out + S1 + S2 + S3 + (long)b * (12 * 1024)
                        + (long)(c * 4) * 1024
                        + (long)(ti * 8) * 32 + tj * 8;

        const int tx = tid & 1;       // 2 thread-cols * 4 px = 8
        const int ty = tid >> 1;      // 0..7

        const float4* s3v = reinterpret_cast<const float4*>(s3);  // 4 f4/row
        float4 p0 = s3v[(2 * ty) * 4 + 2 * tx];
        float4 p1 = s3v[(2 * ty) * 4 + 2 * tx + 1];
        float4 q0 = s3v[(2 * ty + 1) * 4 + 2 * tx];
        float4 q1 = s3v[(2 * ty + 1) * 4 + 2 * tx + 1];

        float4 LL, LH, HL, HH;
        HAAR4(p0, p1, q0, q1, LL, LH, HL, HH);

        float* orow = o4 + (long)ty * 32 + tx * 4;
        __stcs(reinterpret_cast<float4*>(orow),             LL);
        __stcs(reinterpret_cast<float4*>(orow + 1024),      LH);
        __stcs(reinterpret_cast<float4*>(orow + 2 * 1024),  HL);
        __stcs(reinterpret_cast<float4*>(orow + 3 * 1024),  HH);

        if (c == 1) {   // b4 = g4 -> channels 8..11
            float* orow2 = orow + 4 * 1024;
            __stcs(reinterpret_cast<float4*>(orow2),             LL);
            __stcs(reinterpret_cast<float4*>(orow2 + 1024),      LH);
            __stcs(reinterpret_cast<float4*>(orow2 + 2 * 1024),  HL);
            __stcs(reinterpret_cast<float4*>(orow2 + 3 * 1024),  HH);
        }
    }
}

extern "C" void kernel_launch(void* const* d_in, const int* in_sizes, int n_in,
                              void* d_out, int out_size)
{
    const float* x = (const float*)d_in[0];
    float* out = (float*)d_out;

    dim3 block(256, 1, 1);
    dim3 grid(4, 4, 96);
    dwt_fused_kernel<<<grid, block>>>(x, out);
}